// round 2
// baseline (speedup 1.0000x reference)
#include <cuda_runtime.h>

#define DD 768
#define HH 64
#define EE 20
#define TILE_M 128
#define KC 32
#define NCHUNK (DD / KC)

// Precomputed fold products (device globals: no allocation allowed)
__device__ float g_Wc[DD * HH];     // W1_mem + ment (.) W1_hadamard   [768 x 64]
__device__ float g_bias[HH];        // b1 + ment @ W1_mention          [64]
__device__ float g_dist[10 * HH];   // dist_table @ W1_dist            [10 x 64]
__device__ float g_cnt[10 * HH];    // counter_table @ W1_cnt          [10 x 64]

__global__ void precompute_wc(const float* __restrict__ ment, const float* __restrict__ W1) {
    int idx = blockIdx.x * 256 + threadIdx.x;
    if (idx < DD * HH) {
        int d = idx >> 6;
        g_Wc[idx] = W1[idx] + ment[d] * W1[(2 * DD) * HH + idx];
    }
}

__global__ void precompute_small(const float* __restrict__ ment, const float* __restrict__ W1,
                                 const float* __restrict__ b1, const float* __restrict__ dist_t,
                                 const float* __restrict__ cnt_t) {
    int t = threadIdx.x;
    if (t < HH) {
        float s = b1[t];
#pragma unroll 8
        for (int d = 0; d < DD; d++) s += ment[d] * W1[(DD + d) * HH + t];
        g_bias[t] = s;
    } else if (t < HH + 10 * HH) {
        int i = t - HH;
        int b = i >> 6, h = i & 63;
        float sd = 0.f, sc = 0.f;
#pragma unroll
        for (int e = 0; e < EE; e++) {
            sd += dist_t[b * EE + e] * W1[(3 * DD + e) * HH + h];
            sc += cnt_t[b * EE + e] * W1[(3 * DD + EE + e) * HH + h];
        }
        g_dist[i] = sd;
        g_cnt[i] = sc;
    }
}

// Exact integer bucket: identity for c<=4, floor(log2(c))+3 above, clamp [0,9]
__device__ __forceinline__ int get_bucket(int c) {
    int b = (c <= 4) ? c : (34 - __clz(c));
    b = b > 9 ? 9 : b;
    return b < 0 ? 0 : b;
}

__device__ __forceinline__ void ffma2(unsigned long long& acc, unsigned long long a, unsigned long long b) {
    asm("fma.rn.f32x2 %0, %1, %2, %0;" : "+l"(acc) : "l"(a), "l"(b));
}
__device__ __forceinline__ unsigned long long dup2(float x) {
    unsigned long long r;
    asm("mov.b64 %0, {%1, %1};" : "=l"(r) : "f"(x));
    return r;
}
__device__ __forceinline__ float2 unpack2(unsigned long long v) {
    float2 f;
    asm("mov.b64 {%0, %1}, %2;" : "=f"(f.x), "=f"(f.y) : "l"(v));
    return f;
}

__global__ __launch_bounds__(256) void main_kernel(
    const float* __restrict__ memv, const int* __restrict__ entc,
    const int* __restrict__ lastm, const int* __restrict__ mstart,
    const float* __restrict__ W2, const float* __restrict__ b2,
    float* __restrict__ out, int M) {
    __shared__ float As[TILE_M * (KC + 1)];
    __shared__ float Ws[KC * HH];
    __shared__ float s_bias[HH], s_w2[HH], s_dist[10 * HH], s_cnt[10 * HH];

    const int t = threadIdx.x;
    const int R0 = blockIdx.x * TILE_M;
    const int SA = KC + 1;  // padded A stride: conflict-free reads

    if (t < HH) { s_bias[t] = g_bias[t]; s_w2[t] = W2[t]; }
    for (int i = t; i < 10 * HH; i += 256) { s_dist[i] = g_dist[i]; s_cnt[i] = g_cnt[i]; }

    const int m4 = (t >> 3) * 4;   // 4 rows per thread (32 groups x 4 = 128)
    const int n8 = (t & 7) * 8;    // 8 cols per thread (8 groups x 8 = 64)

    unsigned long long acc[4][4];
#pragma unroll
    for (int r = 0; r < 4; r++)
#pragma unroll
        for (int p = 0; p < 4; p++) acc[r][p] = 0ULL;

    for (int kc = 0; kc < NCHUNK; kc++) {
        const int d0 = kc * KC;
        // Load A chunk [128 x 32] into smem (stride 33)
#pragma unroll
        for (int p = 0; p < 4; p++) {
            int m = (t >> 3) + p * 32;
            int d4 = (t & 7) * 4;
            int gr = R0 + m;
            float4 v = make_float4(0.f, 0.f, 0.f, 0.f);
            if (gr < M)
                v = *reinterpret_cast<const float4*>(memv + (size_t)gr * DD + d0 + d4);
            float* s = &As[m * SA + d4];
            s[0] = v.x; s[1] = v.y; s[2] = v.z; s[3] = v.w;
        }
        // Load Wc chunk [32 x 64] (L2-resident)
#pragma unroll
        for (int p = 0; p < 2; p++) {
            int k = (t >> 4) + p * 16;
            int n4 = (t & 15) * 4;
            *reinterpret_cast<float4*>(&Ws[k * HH + n4]) =
                *reinterpret_cast<const float4*>(&g_Wc[(d0 + k) * HH + n4]);
        }
        __syncthreads();
#pragma unroll 8
        for (int k = 0; k < KC; k++) {
            const float* ap = &As[m4 * SA + k];
            unsigned long long a0 = dup2(ap[0]);
            unsigned long long a1 = dup2(ap[SA]);
            unsigned long long a2 = dup2(ap[2 * SA]);
            unsigned long long a3 = dup2(ap[3 * SA]);
            const unsigned long long* wp =
                reinterpret_cast<const unsigned long long*>(&Ws[k * HH + n8]);
            unsigned long long w0 = wp[0], w1 = wp[1], w2 = wp[2], w3 = wp[3];
            ffma2(acc[0][0], a0, w0); ffma2(acc[0][1], a0, w1); ffma2(acc[0][2], a0, w2); ffma2(acc[0][3], a0, w3);
            ffma2(acc[1][0], a1, w0); ffma2(acc[1][1], a1, w1); ffma2(acc[1][2], a1, w2); ffma2(acc[1][3], a1, w3);
            ffma2(acc[2][0], a2, w0); ffma2(acc[2][1], a2, w1); ffma2(acc[2][2], a2, w2); ffma2(acc[2][3], a2, w3);
            ffma2(acc[3][0], a3, w0); ffma2(acc[3][1], a3, w1); ffma2(acc[3][2], a3, w2); ffma2(acc[3][3], a3, w3);
        }
        __syncthreads();
    }

    // Epilogue: bias + feature lookups + ReLU + dot W2, reduce 8 lanes/row
    const int gm = R0 + m4;
    if (gm < M) {
        int4 c4 = *reinterpret_cast<const int4*>(entc + gm);
        int4 l4 = *reinterpret_cast<const int4*>(lastm + gm);
        const int ms0 = mstart[0];
        const float b2v = b2[0];
        int cc[4] = {c4.x, c4.y, c4.z, c4.w};
        int ll[4] = {l4.x, l4.y, l4.z, l4.w};
        float res[4];
#pragma unroll
        for (int r = 0; r < 4; r++) {
            int bd = get_bucket(ms0 - ll[r]);
            int bc = get_bucket(cc[r]);
            const float* dh = &s_dist[bd * HH];
            const float* ch = &s_cnt[bc * HH];
            float s = 0.f;
#pragma unroll
            for (int p = 0; p < 4; p++) {
                float2 g = unpack2(acc[r][p]);
                int n0 = n8 + 2 * p;
                float e0 = g.x + s_bias[n0] + dh[n0] + ch[n0];
                float e1 = g.y + s_bias[n0 + 1] + dh[n0 + 1] + ch[n0 + 1];
                s += fmaxf(e0, 0.f) * s_w2[n0] + fmaxf(e1, 0.f) * s_w2[n0 + 1];
            }
#pragma unroll
            for (int o = 4; o > 0; o >>= 1) s += __shfl_xor_sync(0xffffffffu, s, o);
            res[r] = s;
        }
        if ((t & 7) == 0) {
#pragma unroll
            for (int r = 0; r < 4; r++)
                out[gm + r] = (cc[r] > 0) ? (res[r] + b2v) : -10000.0f;
        }
    }
    if (blockIdx.x == 0 && t == 255) out[M] = 0.0f;
}

extern "C" void kernel_launch(void* const* d_in, const int* in_sizes, int n_in,
                              void* d_out, int out_size) {
    const float* ment   = (const float*)d_in[0];
    const float* memv   = (const float*)d_in[1];
    const float* dist_t = (const float*)d_in[2];
    const float* cnt_t  = (const float*)d_in[3];
    const float* W1     = (const float*)d_in[4];
    const float* b1     = (const float*)d_in[5];
    const float* W2     = (const float*)d_in[6];
    const float* b2     = (const float*)d_in[7];
    const int*   entc   = (const int*)d_in[8];
    const int*   lastm  = (const int*)d_in[9];
    const int*   ms     = (const int*)d_in[10];
    int M = in_sizes[8];

    precompute_wc<<<(DD * HH + 255) / 256, 256>>>(ment, W1);
    precompute_small<<<1, HH + 10 * HH>>>(ment, W1, b1, dist_t, cnt_t);
    main_kernel<<<(M + TILE_M - 1) / TILE_M, 256>>>(memv, entc, lastm, ms, W2, b2, (float*)d_out, M);
}

// round 5
// speedup vs baseline: 1.3857x; 1.3857x over previous
#include <cuda_runtime.h>

#define DD 768
#define HH 64
#define EE 20
#define TILE_M 128
#define KC 32
#define NCHUNK (DD / KC)

// Precomputed fold products (device globals: no allocation allowed)
__device__ float g_Wc[DD * HH];     // W1_mem + ment (.) W1_hadamard   [768 x 64]
__device__ float g_bias[HH];        // b1 + ment @ W1_mention          [64]
__device__ float g_dist[10 * HH];   // dist_table @ W1_dist            [10 x 64]
__device__ float g_cnt[10 * HH];    // counter_table @ W1_cnt          [10 x 64]

// One merged precompute kernel:
//   blocks [0, 192):    g_Wc elementwise fold
//   blocks [192, 256):  g_bias[h] = b1[h] + dot(ment, W1_ment[:, h])  (block reduction)
//   blocks [256, 266):  g_dist / g_cnt rows for bucket b
__global__ __launch_bounds__(256) void precompute_all(
    const float* __restrict__ ment, const float* __restrict__ W1,
    const float* __restrict__ b1, const float* __restrict__ dist_t,
    const float* __restrict__ cnt_t) {
    const int t = threadIdx.x;
    const int blk = blockIdx.x;
    if (blk < 192) {
        int idx = blk * 256 + t;
        int d = idx >> 6;
        g_Wc[idx] = W1[idx] + ment[d] * W1[(2 * DD) * HH + idx];
    } else if (blk < 256) {
        const int h = blk - 192;
        float s = 0.f;
#pragma unroll
        for (int j = 0; j < 3; j++) {
            int d = t + 256 * j;
            s += ment[d] * W1[(DD + d) * HH + h];
        }
#pragma unroll
        for (int o = 16; o > 0; o >>= 1) s += __shfl_xor_sync(0xffffffffu, s, o);
        __shared__ float red[8];
        if ((t & 31) == 0) red[t >> 5] = s;
        __syncthreads();
        if (t == 0) {
            float tot = b1[h];
#pragma unroll
            for (int w = 0; w < 8; w++) tot += red[w];
            g_bias[h] = tot;
        }
    } else {
        const int b = blk - 256;
        if (t < 128) {
            const int h = t & 63;
            const float* tab = (t < 64) ? dist_t : cnt_t;
            const int wo = (t < 64) ? (3 * DD) : (3 * DD + EE);
            float s = 0.f;
#pragma unroll
            for (int e = 0; e < EE; e++)
                s += tab[b * EE + e] * W1[(wo + e) * HH + h];
            if (t < 64) g_dist[b * HH + h] = s;
            else        g_cnt[b * HH + h] = s;
        }
    }
}

// Exact integer bucket: identity for c<=4, floor(log2(c))+3 above, clamp [0,9]
__device__ __forceinline__ int get_bucket(int c) {
    int b = (c <= 4) ? c : (34 - __clz(c));
    b = b > 9 ? 9 : b;
    return b < 0 ? 0 : b;
}

__global__ __launch_bounds__(256) void main_kernel(
    const float* __restrict__ memv, const int* __restrict__ entc,
    const int* __restrict__ lastm, const int* __restrict__ mstart,
    const float* __restrict__ W2, const float* __restrict__ b2,
    float* __restrict__ out, int M) {
    __shared__ float As[TILE_M * (KC + 1)];
    __shared__ float Ws[KC * HH];
    __shared__ float s_bias[HH], s_w2[HH], s_dist[10 * HH], s_cnt[10 * HH];

    const int t = threadIdx.x;
    const int R0 = blockIdx.x * TILE_M;
    const int SA = KC + 1;  // padded A stride: conflict-free reads

    if (t < HH) { s_bias[t] = g_bias[t]; s_w2[t] = W2[t]; }
    for (int i = t; i < 10 * HH; i += 256) { s_dist[i] = g_dist[i]; s_cnt[i] = g_cnt[i]; }

    const int m4 = (t >> 3) * 4;   // 4 rows per thread (32 groups x 4 = 128)
    const int n8 = (t & 7) * 8;    // 8 cols per thread (8 groups x 8 = 64)

    float acc[4][8];
#pragma unroll
    for (int r = 0; r < 4; r++)
#pragma unroll
        for (int c = 0; c < 8; c++) acc[r][c] = 0.f;

    for (int kc = 0; kc < NCHUNK; kc++) {
        const int d0 = kc * KC;
        // Load A chunk [128 x 32] into smem (stride 33)
#pragma unroll
        for (int p = 0; p < 4; p++) {
            int m = (t >> 3) + p * 32;
            int d4 = (t & 7) * 4;
            int gr = R0 + m;
            float4 v = make_float4(0.f, 0.f, 0.f, 0.f);
            if (gr < M)
                v = *reinterpret_cast<const float4*>(memv + (size_t)gr * DD + d0 + d4);
            float* s = &As[m * SA + d4];
            s[0] = v.x; s[1] = v.y; s[2] = v.z; s[3] = v.w;
        }
        // Load Wc chunk [32 x 64] (L2-resident)
#pragma unroll
        for (int p = 0; p < 2; p++) {
            int k = (t >> 4) + p * 16;
            int n4 = (t & 15) * 4;
            *reinterpret_cast<float4*>(&Ws[k * HH + n4]) =
                *reinterpret_cast<const float4*>(&g_Wc[(d0 + k) * HH + n4]);
        }
        __syncthreads();
#pragma unroll 4
        for (int k = 0; k < KC; k++) {
            const float* ap = &As[m4 * SA + k];
            const float* wp = &Ws[k * HH + n8];
            float a[4];
            a[0] = ap[0];
            a[1] = ap[SA];
            a[2] = ap[2 * SA];
            a[3] = ap[3 * SA];
            float4 wa = *reinterpret_cast<const float4*>(wp);
            float4 wb = *reinterpret_cast<const float4*>(wp + 4);
            float w[8] = {wa.x, wa.y, wa.z, wa.w, wb.x, wb.y, wb.z, wb.w};
#pragma unroll
            for (int r = 0; r < 4; r++)
#pragma unroll
                for (int c = 0; c < 8; c++)
                    acc[r][c] = fmaf(a[r], w[c], acc[r][c]);
        }
        __syncthreads();
    }

    // Epilogue: bias + feature lookups + ReLU + dot W2, reduce 8 lanes/row
    const int gm = R0 + m4;
    if (gm < M) {
        int4 c4 = *reinterpret_cast<const int4*>(entc + gm);
        int4 l4 = *reinterpret_cast<const int4*>(lastm + gm);
        const int ms0 = mstart[0];
        const float b2v = b2[0];
        int cc[4] = {c4.x, c4.y, c4.z, c4.w};
        int ll[4] = {l4.x, l4.y, l4.z, l4.w};
        float res[4];
#pragma unroll
        for (int r = 0; r < 4; r++) {
            int bd = get_bucket(ms0 - ll[r]);
            int bc = get_bucket(cc[r]);
            const float* dh = &s_dist[bd * HH];
            const float* ch = &s_cnt[bc * HH];
            float s = 0.f;
#pragma unroll
            for (int c = 0; c < 8; c++) {
                int n0 = n8 + c;
                float e = acc[r][c] + s_bias[n0] + dh[n0] + ch[n0];
                s = fmaf(fmaxf(e, 0.f), s_w2[n0], s);
            }
#pragma unroll
            for (int o = 4; o > 0; o >>= 1) s += __shfl_xor_sync(0xffffffffu, s, o);
            res[r] = s;
        }
        if ((t & 7) == 0) {
#pragma unroll
            for (int r = 0; r < 4; r++)
                out[gm + r] = (cc[r] > 0) ? (res[r] + b2v) : -10000.0f;
        }
    }
    if (blockIdx.x == 0 && t == 255) out[M] = 0.0f;
}

extern "C" void kernel_launch(void* const* d_in, const int* in_sizes, int n_in,
                              void* d_out, int out_size) {
    const float* ment   = (const float*)d_in[0];
    const float* memv   = (const float*)d_in[1];
    const float* dist_t = (const float*)d_in[2];
    const float* cnt_t  = (const float*)d_in[3];
    const float* W1     = (const float*)d_in[4];
    const float* b1     = (const float*)d_in[5];
    const float* W2     = (const float*)d_in[6];
    const float* b2     = (const float*)d_in[7];
    const int*   entc   = (const int*)d_in[8];
    const int*   lastm  = (const int*)d_in[9];
    const int*   ms     = (const int*)d_in[10];
    int M = in_sizes[8];

    precompute_all<<<266, 256>>>(ment, W1, b1, dist_t, cnt_t);
    main_kernel<<<(M + TILE_M - 1) / TILE_M, 256>>>(memv, entc, lastm, ms, W2, b2, (float*)d_out, M);
}

// round 7
// speedup vs baseline: 1.8023x; 1.3006x over previous
#include <cuda_runtime.h>

#define DD 768
#define HH 64
#define EE 20
#define TILE_M 128
#define KC 32
#define NCHUNK (DD / KC)

// Precomputed fold products (device globals: no allocation allowed)
__device__ float g_Wc[DD * HH];     // W1_mem + ment (.) W1_hadamard   [768 x 64]
__device__ float g_bias[HH];        // b1 + ment @ W1_mention          [64]
__device__ float g_dist[10 * HH];   // dist_table @ W1_dist            [10 x 64]
__device__ float g_cnt[10 * HH];    // counter_table @ W1_cnt          [10 x 64]

__global__ __launch_bounds__(256) void precompute_all(
    const float* __restrict__ ment, const float* __restrict__ W1,
    const float* __restrict__ b1, const float* __restrict__ dist_t,
    const float* __restrict__ cnt_t) {
    const int t = threadIdx.x;
    const int blk = blockIdx.x;
    if (blk < 192) {
        int idx = blk * 256 + t;
        int d = idx >> 6;
        g_Wc[idx] = W1[idx] + ment[d] * W1[(2 * DD) * HH + idx];
    } else if (blk < 256) {
        const int h = blk - 192;
        float s = 0.f;
#pragma unroll
        for (int j = 0; j < 3; j++) {
            int d = t + 256 * j;
            s += ment[d] * W1[(DD + d) * HH + h];
        }
#pragma unroll
        for (int o = 16; o > 0; o >>= 1) s += __shfl_xor_sync(0xffffffffu, s, o);
        __shared__ float red[8];
        if ((t & 31) == 0) red[t >> 5] = s;
        __syncthreads();
        if (t == 0) {
            float tot = b1[h];
#pragma unroll
            for (int w = 0; w < 8; w++) tot += red[w];
            g_bias[h] = tot;
        }
    } else {
        const int b = blk - 256;
        if (t < 128) {
            const int h = t & 63;
            const float* tab = (t < 64) ? dist_t : cnt_t;
            const int wo = (t < 64) ? (3 * DD) : (3 * DD + EE);
            float s = 0.f;
#pragma unroll
            for (int e = 0; e < EE; e++)
                s += tab[b * EE + e] * W1[(wo + e) * HH + h];
            if (t < 64) g_dist[b * HH + h] = s;
            else        g_cnt[b * HH + h] = s;
        }
    }
}

// Exact integer bucket: identity for c<=4, floor(log2(c))+3 above, clamp [0,9]
__device__ __forceinline__ int get_bucket(int c) {
    int b = (c <= 4) ? c : (34 - __clz(c));
    b = b > 9 ? 9 : b;
    return b < 0 ? 0 : b;
}

// A^T smem swizzle: chunk' = chunk ^ s(k); s distinct (mod 8) over k-steps of 4
__device__ __forceinline__ int swz(int k) {
    return ((k >> 2) ^ ((k & 1) << 2)) & 7;
}

__global__ __launch_bounds__(256, 3) void main_kernel(
    const float* __restrict__ memv, const int* __restrict__ entc,
    const int* __restrict__ lastm, const int* __restrict__ mstart,
    const float* __restrict__ W2, const float* __restrict__ b2,
    float* __restrict__ out, int M) {
    __shared__ float AsT[KC * TILE_M];          // transposed A tile, swizzled
    __shared__ float Ws[KC * HH];               // W tile, plain [k][n]
    __shared__ float s_bias[HH], s_w2[HH], s_dist[10 * HH], s_cnt[10 * HH];

    const int t = threadIdx.x;
    const int R0 = blockIdx.x * TILE_M;

    if (t < HH) { s_bias[t] = g_bias[t]; s_w2[t] = W2[t]; }
    for (int i = t; i < 10 * HH; i += 256) { s_dist[i] = g_dist[i]; s_cnt[i] = g_cnt[i]; }

    const int rg = t >> 3;         // 0..31: row-group; rows m4..m4+3
    const int m4 = rg * 4;
    const int nl = t & 7;          // 0..7: column lane
    const int nA = nl * 4;         // owns cols [nA, nA+3] and [32+nA, 32+nA+3]
    const int d4 = nl * 4;         // k-offset of this thread's global A float4

    float acc[4][8];
#pragma unroll
    for (int r = 0; r < 4; r++)
#pragma unroll
        for (int c = 0; c < 8; c++) acc[r][c] = 0.f;

    float4 aNext[4];
    float4 wNext[2];

    // --- staging helpers (inlined via lambdas) ---
    auto load_next = [&](int kc) {
        const int d0 = kc * KC;
#pragma unroll
        for (int p = 0; p < 4; p++) {
            int gr = R0 + rg + p * 32;
            if (gr < M)
                aNext[p] = *reinterpret_cast<const float4*>(memv + (size_t)gr * DD + d0 + d4);
            else
                aNext[p] = make_float4(0.f, 0.f, 0.f, 0.f);
        }
#pragma unroll
        for (int p = 0; p < 2; p++) {
            int k = (t >> 4) + p * 16;
            int n4 = (t & 15) * 4;
            wNext[p] = *reinterpret_cast<const float4*>(&g_Wc[(d0 + k) * HH + n4]);
        }
    };
    auto commit = [&]() {
#pragma unroll
        for (int p = 0; p < 4; p++) {
            int row = rg + p * 32;
            int chunk = row >> 2, off = row & 3;
            float v[4] = {aNext[p].x, aNext[p].y, aNext[p].z, aNext[p].w};
#pragma unroll
            for (int j = 0; j < 4; j++) {
                int k = d4 + j;
                AsT[k * TILE_M + ((chunk ^ swz(k)) << 2) + off] = v[j];
            }
        }
#pragma unroll
        for (int p = 0; p < 2; p++) {
            int k = (t >> 4) + p * 16;
            int n4 = (t & 15) * 4;
            *reinterpret_cast<float4*>(&Ws[k * HH + n4]) = wNext[p];
        }
    };

    load_next(0);
    commit();
    __syncthreads();

    for (int kc = 0; kc < NCHUNK; kc++) {
        if (kc + 1 < NCHUNK) load_next(kc + 1);
#pragma unroll 4
        for (int k = 0; k < KC; k++) {
            // A: one LDS.128 -> 4 rows (swizzled, conflict-free)
            float4 av = *reinterpret_cast<const float4*>(
                &AsT[k * TILE_M + ((rg ^ swz(k)) << 2)]);
            // W: two contiguous-128B LDS.128 (conflict-free)
            float4 wa = *reinterpret_cast<const float4*>(&Ws[k * HH + nA]);
            float4 wb = *reinterpret_cast<const float4*>(&Ws[k * HH + 32 + nA]);
            float a[4] = {av.x, av.y, av.z, av.w};
            float w[8] = {wa.x, wa.y, wa.z, wa.w, wb.x, wb.y, wb.z, wb.w};
#pragma unroll
            for (int r = 0; r < 4; r++)
#pragma unroll
                for (int c = 0; c < 8; c++)
                    acc[r][c] = fmaf(a[r], w[c], acc[r][c]);
        }
        if (kc + 1 < NCHUNK) {
            __syncthreads();
            commit();
            __syncthreads();
        }
    }

    // Epilogue: bias + feature lookups + ReLU + dot W2, reduce 8 lanes/row
    const int gm = R0 + m4;
    if (gm < M) {
        int4 c4 = *reinterpret_cast<const int4*>(entc + gm);
        int4 l4 = *reinterpret_cast<const int4*>(lastm + gm);
        const int ms0 = mstart[0];
        const float b2v = b2[0];
        int cc[4] = {c4.x, c4.y, c4.z, c4.w};
        int ll[4] = {l4.x, l4.y, l4.z, l4.w};
        float res[4];
#pragma unroll
        for (int r = 0; r < 4; r++) {
            int bd = get_bucket(ms0 - ll[r]);
            int bc = get_bucket(cc[r]);
            const float* dh = &s_dist[bd * HH];
            const float* ch = &s_cnt[bc * HH];
            float s = 0.f;
#pragma unroll
            for (int c = 0; c < 8; c++) {
                int n0 = (c < 4) ? (nA + c) : (32 + nA + c - 4);
                float e = acc[r][c] + s_bias[n0] + dh[n0] + ch[n0];
                s = fmaf(fmaxf(e, 0.f), s_w2[n0], s);
            }
#pragma unroll
            for (int o = 4; o > 0; o >>= 1) s += __shfl_xor_sync(0xffffffffu, s, o);
            res[r] = s;
        }
        if (nl == 0) {
#pragma unroll
            for (int r = 0; r < 4; r++)
                out[gm + r] = (cc[r] > 0) ? (res[r] + b2v) : -10000.0f;
        }
    }
    if (blockIdx.x == 0 && t == 255) out[M] = 0.0f;
}

extern "C" void kernel_launch(void* const* d_in, const int* in_sizes, int n_in,
                              void* d_out, int out_size) {
    const float* ment   = (const float*)d_in[0];
    const float* memv   = (const float*)d_in[1];
    const float* dist_t = (const float*)d_in[2];
    const float* cnt_t  = (const float*)d_in[3];
    const float* W1     = (const float*)d_in[4];
    const float* b1     = (const float*)d_in[5];
    const float* W2     = (const float*)d_in[6];
    const float* b2     = (const float*)d_in[7];
    const int*   entc   = (const int*)d_in[8];
    const int*   lastm  = (const int*)d_in[9];
    const int*   ms     = (const int*)d_in[10];
    int M = in_sizes[8];

    precompute_all<<<266, 256>>>(ment, W1, b1, dist_t, cnt_t);
    main_kernel<<<(M + TILE_M - 1) / TILE_M, 256>>>(memv, entc, lastm, ms, W2, b2, (float*)d_out, M);
}

// round 9
// speedup vs baseline: 3.3846x; 1.8779x over previous
#include <cuda_runtime.h>
#include <cstdint>

#define DD 768
#define HH 64
#define EE 20
#define TILE_M 128
#define KC 32
#define NCHUNK (DD / KC)
#define SA 36                      // A smem stride (floats), conflict-free frags
#define SB 72                      // B smem stride (floats), conflict-free frags
#define A_FLOATS (TILE_M * SA)     // 4608 per buffer
#define B_FLOATS (KC * SB)         // 2304 per buffer
#define SMEM_FLOATS (2 * A_FLOATS + 2 * B_FLOATS + 64 + 64 + 640 + 640)
#define SMEM_BYTES (SMEM_FLOATS * 4)

// Precomputed fold products (device globals: no allocation allowed)
__device__ float g_Wc[DD * HH];     // W1_mem + ment (.) W1_hadamard   [768 x 64]
__device__ float g_bias[HH];        // b1 + ment @ W1_mention          [64]
__device__ float g_dist[10 * HH];   // dist_table @ W1_dist            [10 x 64]
__device__ float g_cnt[10 * HH];    // counter_table @ W1_cnt          [10 x 64]

__global__ __launch_bounds__(256) void precompute_all(
    const float* __restrict__ ment, const float* __restrict__ W1,
    const float* __restrict__ b1, const float* __restrict__ dist_t,
    const float* __restrict__ cnt_t) {
    const int t = threadIdx.x;
    const int blk = blockIdx.x;
    if (blk < 192) {
        int idx = blk * 256 + t;
        int d = idx >> 6;
        g_Wc[idx] = W1[idx] + ment[d] * W1[(2 * DD) * HH + idx];
    } else if (blk < 256) {
        const int h = blk - 192;
        float s = 0.f;
#pragma unroll
        for (int j = 0; j < 3; j++) {
            int d = t + 256 * j;
            s += ment[d] * W1[(DD + d) * HH + h];
        }
#pragma unroll
        for (int o = 16; o > 0; o >>= 1) s += __shfl_xor_sync(0xffffffffu, s, o);
        __shared__ float red[8];
        if ((t & 31) == 0) red[t >> 5] = s;
        __syncthreads();
        if (t == 0) {
            float tot = b1[h];
#pragma unroll
            for (int w = 0; w < 8; w++) tot += red[w];
            g_bias[h] = tot;
        }
    } else {
        const int b = blk - 256;
        if (t < 128) {
            const int h = t & 63;
            const float* tab = (t < 64) ? dist_t : cnt_t;
            const int wo = (t < 64) ? (3 * DD) : (3 * DD + EE);
            float s = 0.f;
#pragma unroll
            for (int e = 0; e < EE; e++)
                s += tab[b * EE + e] * W1[(wo + e) * HH + h];
            if (t < 64) g_dist[b * HH + h] = s;
            else        g_cnt[b * HH + h] = s;
        }
    }
}

// Exact integer bucket: identity for c<=4, floor(log2(c))+3 above, clamp [0,9]
__device__ __forceinline__ int get_bucket(int c) {
    int b = (c <= 4) ? c : (34 - __clz(c));
    b = b > 9 ? 9 : b;
    return b < 0 ? 0 : b;
}

__device__ __forceinline__ uint32_t f2tf32(float f) {
    uint32_t r;
    asm("cvt.rna.tf32.f32 %0, %1;" : "=r"(r) : "f"(f));
    return r;
}

__device__ __forceinline__ void mma_tf32(float* d, const uint32_t* a, uint32_t b0, uint32_t b1) {
    asm volatile(
        "mma.sync.aligned.m16n8k8.row.col.f32.tf32.tf32.f32 "
        "{%0,%1,%2,%3},{%4,%5,%6,%7},{%8,%9},{%0,%1,%2,%3};"
        : "+f"(d[0]), "+f"(d[1]), "+f"(d[2]), "+f"(d[3])
        : "r"(a[0]), "r"(a[1]), "r"(a[2]), "r"(a[3]), "r"(b0), "r"(b1));
}

__device__ __forceinline__ void cpa16(uint32_t saddr, const void* gaddr) {
    asm volatile("cp.async.cg.shared.global [%0], [%1], 16;" :: "r"(saddr), "l"(gaddr));
}
__device__ __forceinline__ void cpa_commit() { asm volatile("cp.async.commit_group;"); }
template <int N> __device__ __forceinline__ void cpa_wait() {
    asm volatile("cp.async.wait_group %0;" :: "n"(N));
}

extern __shared__ float smem[];

__global__ __launch_bounds__(128, 3) void main_kernel(
    const float* __restrict__ memv, const int* __restrict__ entc,
    const int* __restrict__ lastm, const int* __restrict__ mstart,
    const float* __restrict__ W2, const float* __restrict__ b2,
    float* __restrict__ out, int M) {
    float* As = smem;                         // [2][128][SA]
    float* Ws = smem + 2 * A_FLOATS;          // [2][32][SB]
    float* s_bias = smem + 2 * A_FLOATS + 2 * B_FLOATS;
    float* s_w2 = s_bias + 64;
    float* s_dist = s_w2 + 64;
    float* s_cnt = s_dist + 640;

    const int t = threadIdx.x;
    const int w = t >> 5, lane = t & 31;
    const int g = lane >> 2, c = lane & 3;
    const int R0 = blockIdx.x * TILE_M;

    if (t < 64) { s_bias[t] = g_bias[t]; s_w2[t] = W2[t]; }
    for (int i = t; i < 640; i += 128) { s_dist[i] = g_dist[i]; s_cnt[i] = g_cnt[i]; }

    const uint32_t sA = (uint32_t)__cvta_generic_to_shared(As);
    const uint32_t sB = (uint32_t)__cvta_generic_to_shared(Ws);

    // --- async chunk copy: global -> smem buffer b ---
    auto copy_chunk = [&](int b, int kc) {
        const int d0 = kc * KC;
        int row = t;
        if (R0 + row < M) {
            uint32_t dst = sA + (b * A_FLOATS + row * SA) * 4;
            const float* src = memv + (size_t)(R0 + row) * DD + d0;
#pragma unroll
            for (int j = 0; j < 8; j++) cpa16(dst + 16 * j, src + 4 * j);
        }
        int k = t >> 2, nq = (t & 3) * 16;
        uint32_t dstB = sB + (b * B_FLOATS + k * SB + nq) * 4;
        const float* srcB = g_Wc + (d0 + k) * HH + nq;
#pragma unroll
        for (int j = 0; j < 4; j++) cpa16(dstB + 16 * j, srcB + 4 * j);
    };

    float acc[2][8][4];
#pragma unroll
    for (int mt = 0; mt < 2; mt++)
#pragma unroll
        for (int nt = 0; nt < 8; nt++)
#pragma unroll
            for (int i = 0; i < 4; i++) acc[mt][nt][i] = 0.f;

    const int r0 = w * 32;

    copy_chunk(0, 0);
    cpa_commit();

    int buf = 0;
    for (int kc = 0; kc < NCHUNK; kc++) {
        if (kc + 1 < NCHUNK) {
            copy_chunk(buf ^ 1, kc + 1);
            cpa_commit();
            cpa_wait<1>();
        } else {
            cpa_wait<0>();
        }
        __syncthreads();

        const float* A = As + buf * A_FLOATS;
        const float* B = Ws + buf * B_FLOATS;
#pragma unroll
        for (int kt = 0; kt < 4; kt++) {
            const int k0 = kt * 8;
            uint32_t a[2][4];
#pragma unroll
            for (int mt = 0; mt < 2; mt++) {
                const float* ap = A + (r0 + 16 * mt + g) * SA + k0 + c;
                a[mt][0] = f2tf32(ap[0]);
                a[mt][1] = f2tf32(ap[8 * SA]);
                a[mt][2] = f2tf32(ap[4]);
                a[mt][3] = f2tf32(ap[8 * SA + 4]);
            }
#pragma unroll
            for (int nt = 0; nt < 8; nt++) {
                const float* bp = B + (k0 + c) * SB + nt * 8 + g;
                uint32_t b0 = f2tf32(bp[0]);
                uint32_t b1 = f2tf32(bp[4 * SB]);
                mma_tf32(acc[0][nt], a[0], b0, b1);
                mma_tf32(acc[1][nt], a[1], b0, b1);
            }
        }
        __syncthreads();
        buf ^= 1;
    }

    // Epilogue: bias + feature lookups + ReLU + dot W2; quad-reduce per row
    const int ms0 = mstart[0];
    const float b2v = b2[0];
#pragma unroll
    for (int mt = 0; mt < 2; mt++) {
#pragma unroll
        for (int half = 0; half < 2; half++) {
            int r = r0 + 16 * mt + 8 * half + g;
            int gm = R0 + r;
            int gmc = (gm < M) ? gm : 0;
            int cnt_v = entc[gmc];
            int bd = get_bucket(ms0 - lastm[gmc]);
            int bc = get_bucket(cnt_v);
            const float* dh = &s_dist[bd * HH];
            const float* ch = &s_cnt[bc * HH];
            float s = 0.f;
#pragma unroll
            for (int nt = 0; nt < 8; nt++) {
                int col = 8 * nt + 2 * c;
                float v0 = acc[mt][nt][2 * half + 0];
                float v1 = acc[mt][nt][2 * half + 1];
                float e0 = v0 + s_bias[col] + dh[col] + ch[col];
                float e1 = v1 + s_bias[col + 1] + dh[col + 1] + ch[col + 1];
                s = fmaf(fmaxf(e0, 0.f), s_w2[col], s);
                s = fmaf(fmaxf(e1, 0.f), s_w2[col + 1], s);
            }
            s += __shfl_xor_sync(0xffffffffu, s, 1);
            s += __shfl_xor_sync(0xffffffffu, s, 2);
            if (c == 0 && gm < M)
                out[gm] = (cnt_v > 0) ? (s + b2v) : -10000.0f;
        }
    }
    if (blockIdx.x == 0 && t == 0) out[M] = 0.0f;
}

extern "C" void kernel_launch(void* const* d_in, const int* in_sizes, int n_in,
                              void* d_out, int out_size) {
    const float* ment   = (const float*)d_in[0];
    const float* memv   = (const float*)d_in[1];
    const float* dist_t = (const float*)d_in[2];
    const float* cnt_t  = (const float*)d_in[3];
    const float* W1     = (const float*)d_in[4];
    const float* b1     = (const float*)d_in[5];
    const float* W2     = (const float*)d_in[6];
    const float* b2     = (const float*)d_in[7];
    const int*   entc   = (const int*)d_in[8];
    const int*   lastm  = (const int*)d_in[9];
    const int*   ms     = (const int*)d_in[10];
    int M = in_sizes[8];

    cudaFuncSetAttribute(main_kernel, cudaFuncAttributeMaxDynamicSharedMemorySize, SMEM_BYTES);
    precompute_all<<<266, 256>>>(ment, W1, b1, dist_t, cnt_t);
    main_kernel<<<(M + TILE_M - 1) / TILE_M, 128, SMEM_BYTES>>>(
        memv, entc, lastm, ms, W2, b2, (float*)d_out, M);
}